// round 14
// baseline (speedup 1.0000x reference)
#include <cuda_runtime.h>
#include <cuda_bf16.h>
#include <cstdint>

#define BB 8
#define NN 8192
#define CIN 64
#define CO 128
#define SS 2048
#define KK 16

typedef unsigned long long ull;

// ---------------- scratch (static device globals; no allocation) ----------------
__device__ float g_y1[(size_t)BB * CO * NN];     // conv1 pre-BN   [B][C][N]
__device__ float g_y2[(size_t)BB * CO * NN];     // conv2 pre-BN   [B][C][N]
__device__ float g_f2[(size_t)BB * NN * CO];     // conv2 post-BN  [B][N][C] (transposed)
__device__ float g_a1[CO], g_b1s[CO], g_a2[CO], g_b2s[CO];
__device__ float g_ps[2][CO][BB], g_pq[2][CO][BB];   // stats partials
__device__ int   g_knn[(size_t)BB * SS * KK];

// ---------------- packed f32x2 helpers (per-lane RN, identical to scalar) --------
__device__ __forceinline__ ull f2add(ull a, ull b) {
    ull r; asm("add.rn.f32x2 %0,%1,%2;" : "=l"(r) : "l"(a), "l"(b)); return r;
}
__device__ __forceinline__ ull f2mul(ull a, ull b) {
    ull r; asm("mul.rn.f32x2 %0,%1,%2;" : "=l"(r) : "l"(a), "l"(b)); return r;
}
__device__ __forceinline__ ull pack2(float lo, float hi) {
    ull r; asm("mov.b64 %0,{%1,%2};" : "=l"(r) : "f"(lo), "f"(hi)); return r;
}
__device__ __forceinline__ float2 unpack2(ull v) {
    float2 r; asm("mov.b64 {%0,%1},%2;" : "=f"(r.x), "=f"(r.y) : "l"(v)); return r;
}

// =================================================================================
// FPS (R9 skeleton, 256 threads x 32 points): one CTA per batch, packed f32x2,
// 2 barriers/iter, ping-pong atomicMax(float-bits) + lazy rescan + atomicMin.
// 8 warps: barrier drain and same-address atomic chains shrink again; per-SMSP
// update issue work invariant; ILP stays high (16 independent chains/thread).
// Distance formula matches reference bit-exactly: (dx*dx + dy*dy) + dz*dz, no FMA.
// =================================================================================
__global__ __launch_bounds__(256, 1) void fps_kernel(const float* __restrict__ points,
                                                     float* __restrict__ cent)
{
    __shared__ int sMaxI[2];   // float-bits of global max (dd >= 0 -> int order ok)
    __shared__ int sIdx[2];    // argmax index (first-index tiebreak)

    const int b = blockIdx.x;
    const int t = threadIdx.x;
    const int lane = t & 31;
    const float* P = points + (size_t)b * 3 * NN;
    float* C = cent + (size_t)b * 3 * SS;

    if (t == 0) { sMaxI[0] = 0; sMaxI[1] = 0; sIdx[0] = 0x7fffffff; sIdx[1] = 0x7fffffff; }

    const float x0 = __ldg(&P[0]);
    const float y0 = __ldg(&P[NN]);
    const float z0 = __ldg(&P[2 * NN]);
    const ull nx0 = pack2(-x0, -x0), ny0 = pack2(-y0, -y0), nz0 = pack2(-z0, -z0);

    // point pair q of this thread covers global points 2*(t+256*q) and +1
    const float2* Px = (const float2*)P;
    const float2* Py = (const float2*)(P + NN);
    const float2* Pz = (const float2*)(P + 2 * NN);

    ull px[16], py[16], pz[16];
    float dd[32];
#pragma unroll
    for (int q = 0; q < 16; q++) {
        const int i = t + 256 * q;
        const float2 vx = Px[i], vy = Py[i], vz = Pz[i];
        px[q] = pack2(vx.x, vx.y); py[q] = pack2(vy.x, vy.y); pz[q] = pack2(vz.x, vz.y);
        const ull dx = f2add(px[q], nx0);
        const ull dy = f2add(py[q], ny0);
        const ull dz = f2add(pz[q], nz0);
        const ull s = f2add(f2add(f2mul(dx, dx), f2mul(dy, dy)), f2mul(dz, dz));
        const float2 sv = unpack2(s);
        dd[2 * q] = sv.x; dd[2 * q + 1] = sv.y;
    }
    // warp max: per-thread fmax tree + one REDUX
    float wm;
    {
        float m = fmaxf(dd[0], dd[1]);
#pragma unroll
        for (int j = 2; j < 32; j += 2) m = fmaxf(m, fmaxf(dd[j], dd[j + 1]));
        wm = __uint_as_float(__reduce_max_sync(0xffffffffu, __float_as_uint(m)));
    }

    if (t == 0) { C[0] = x0; C[SS] = y0; C[2 * SS] = z0; }
    __syncthreads();   // slot init visible; first wm ready

    for (int s = 1; s < SS; s++) {
        const int c = s & 1;
        if (lane == 0) atomicMax(&sMaxI[c], __float_as_int(wm));
        __syncthreads();                                   // bar1
        const float gm = __int_as_float(sMaxI[c]);
        if (t == 0) { sMaxI[c ^ 1] = 0; sIdx[c ^ 1] = 0x7fffffff; }  // reset other slot
        if (wm == gm) {                                    // warp-uniform branch (~1 warp)
            int mi = 0x7fffffff;
#pragma unroll
            for (int q = 0; q < 16; q++) {
                const int base = 2 * (t + 256 * q);
                if (dd[2 * q] == gm)     mi = min(mi, base);
                if (dd[2 * q + 1] == gm) mi = min(mi, base + 1);
            }
            if (mi != 0x7fffffff) atomicMin(&sIdx[c], mi); // first-index tiebreak
        }
        __syncthreads();                                   // bar2
        const int widx = sIdx[c];
        const float cx = __ldg(&P[widx]);
        const float cy = __ldg(&P[NN + widx]);
        const float cz = __ldg(&P[2 * NN + widx]);
        if (t == 0) { C[s] = cx; C[SS + s] = cy; C[2 * SS + s] = cz; }

        const ull ncx = pack2(-cx, -cx), ncy = pack2(-cy, -cy), ncz = pack2(-cz, -cz);
#pragma unroll
        for (int q = 0; q < 16; q++) {
            const ull dx = f2add(px[q], ncx);
            const ull dy = f2add(py[q], ncy);
            const ull dz = f2add(pz[q], ncz);
            const ull d2 = f2add(f2add(f2mul(dx, dx), f2mul(dy, dy)), f2mul(dz, dz));
            const float2 dv = unpack2(d2);
            dd[2 * q]     = fminf(dd[2 * q], dv.x);
            dd[2 * q + 1] = fminf(dd[2 * q + 1], dv.y);
        }
        float m = fmaxf(dd[0], dd[1]);
#pragma unroll
        for (int j = 2; j < 32; j += 2) m = fmaxf(m, fmaxf(dd[j], dd[j + 1]));
        wm = __uint_as_float(__reduce_max_sync(0xffffffffu, __float_as_uint(m)));
    }
}

// =================================================================================
// GEMM1: y1[b][o][n] = W1[o][:] . feats[b][:][n] + b1[o]      (128x64 @ 64xN)
// =================================================================================
__global__ __launch_bounds__(256) void gemm1_kernel(const float* __restrict__ feats,
                                                    const float* __restrict__ W1,
                                                    const float* __restrict__ b1)
{
    __shared__ float As[CIN][CO];   // As[k][o]  (W transposed)
    __shared__ float Xs[CIN][64];
    const int b = blockIdx.y;
    const int n0 = blockIdx.x * 64;
    const int tid = threadIdx.x;
    const int tx = tid & 15, ty = tid >> 4;

    const float4* W4 = (const float4*)W1;                  // [128][16] float4
#pragma unroll
    for (int q = 0; q < 8; q++) {
        const int f = tid + 256 * q;                       // 0..2047
        const int o = f & 127;
        const int kq = f >> 7;                             // 0..15
        const float4 w = W4[o * 16 + kq];
        As[kq * 4 + 0][o] = w.x; As[kq * 4 + 1][o] = w.y;
        As[kq * 4 + 2][o] = w.z; As[kq * 4 + 3][o] = w.w;
    }
    const float* X = feats + (size_t)b * CIN * NN + n0;
#pragma unroll
    for (int r = 0; r < 16; r++) {
        const int e = tid + 256 * r;                       // 0..4095
        const int c = e >> 6, j = e & 63;
        Xs[c][j] = X[(size_t)c * NN + j];
    }
    __syncthreads();

    float acc[8][4];
#pragma unroll
    for (int i = 0; i < 8; i++)
#pragma unroll
        for (int j = 0; j < 4; j++) acc[i][j] = 0.f;

    const int ro = ty * 4, co = tx * 4;
#pragma unroll 4
    for (int k = 0; k < CIN; k++) {
        float a[8], bv[4];
        *(float4*)&a[0] = *(const float4*)&As[k][ro];
        *(float4*)&a[4] = *(const float4*)&As[k][ro + 64];
        *(float4*)&bv[0] = *(const float4*)&Xs[k][co];
#pragma unroll
        for (int i = 0; i < 8; i++)
#pragma unroll
            for (int j = 0; j < 4; j++) acc[i][j] = fmaf(a[i], bv[j], acc[i][j]);
    }

    float* Y = g_y1 + (size_t)b * CO * NN + n0;
#pragma unroll
    for (int i = 0; i < 8; i++) {
        const int o = (i < 4) ? (ro + i) : (64 + ro + i - 4);
        const float bias = __ldg(&b1[o]);
        float4 v = make_float4(acc[i][0] + bias, acc[i][1] + bias,
                               acc[i][2] + bias, acc[i][3] + bias);
        *(float4*)&Y[(size_t)o * NN + co] = v;
    }
}

// =================================================================================
// BN stats, two-stage. Stage A: grid (CO, BB) partial sums. Stage B: finalize.
// =================================================================================
__global__ __launch_bounds__(256) void stats_part_kernel(int which)
{
    const float* y = which ? g_y2 : g_y1;
    const int c = blockIdx.x, b = blockIdx.y, t = threadIdx.x;
    const int lane = t & 31, warp = t >> 5;
    const float* p = y + ((size_t)b * CO + c) * NN;
    float s = 0.f, q = 0.f;
    for (int i = t; i < NN; i += 256) { const float v = p[i]; s += v; q = fmaf(v, v, q); }
#pragma unroll
    for (int o = 16; o; o >>= 1) {
        s += __shfl_xor_sync(0xffffffffu, s, o);
        q += __shfl_xor_sync(0xffffffffu, q, o);
    }
    __shared__ float ss[8], qs[8];
    if (lane == 0) { ss[warp] = s; qs[warp] = q; }
    __syncthreads();
    if (t == 0) {
        float S = 0.f, Q = 0.f;
#pragma unroll
        for (int w = 0; w < 8; w++) { S += ss[w]; Q += qs[w]; }
        g_ps[which][c][b] = S; g_pq[which][c][b] = Q;
    }
}

__global__ __launch_bounds__(CO) void stats_fin_kernel(const float* __restrict__ gamma,
                                                       const float* __restrict__ beta,
                                                       int which)
{
    const int c = threadIdx.x;
    float S = 0.f, Q = 0.f;
#pragma unroll
    for (int b = 0; b < BB; b++) { S += g_ps[which][c][b]; Q += g_pq[which][c][b]; }
    const float mean = S * (1.f / 65536.f);
    const float var = Q * (1.f / 65536.f) - mean * mean;
    const float inv = rsqrtf(fmaxf(var, 0.f) + 1e-5f);
    const float av = gamma[c] * inv;
    if (which) { g_a2[c] = av; g_b2s[c] = beta[c] - mean * av; }
    else       { g_a1[c] = av; g_b1s[c] = beta[c] - mean * av; }
}

// =================================================================================
// GEMM2 with fused BN1+ReLU applied to the input tile   (128x128 @ 128xN)
// =================================================================================
__global__ __launch_bounds__(256) void gemm2_kernel(const float* __restrict__ W2,
                                                    const float* __restrict__ b2)
{
    __shared__ float As[64][CO];
    __shared__ float Xs[64][64];
    const int b = blockIdx.y, n0 = blockIdx.x * 64;
    const int tid = threadIdx.x, tx = tid & 15, ty = tid >> 4;

    float acc[8][4];
#pragma unroll
    for (int i = 0; i < 8; i++)
#pragma unroll
        for (int j = 0; j < 4; j++) acc[i][j] = 0.f;

    const float4* W4 = (const float4*)W2;                  // [128][32] float4
    const float* Ybase = g_y1 + (size_t)b * CO * NN + n0;
    const int ro = ty * 4, co = tx * 4;

    for (int kt = 0; kt < 2; kt++) {
        if (kt) __syncthreads();
#pragma unroll
        for (int q = 0; q < 8; q++) {
            const int f = tid + 256 * q;
            const int o = f & 127;
            const int kq = f >> 7;
            const float4 w = W4[o * 32 + kt * 16 + kq];
            As[kq * 4 + 0][o] = w.x; As[kq * 4 + 1][o] = w.y;
            As[kq * 4 + 2][o] = w.z; As[kq * 4 + 3][o] = w.w;
        }
#pragma unroll
        for (int r = 0; r < 16; r++) {
            const int e = tid + 256 * r;
            const int cl = e >> 6, j = e & 63;
            const int c = kt * 64 + cl;
            const float v = Ybase[(size_t)c * NN + j];
            Xs[cl][j] = fmaxf(fmaf(g_a1[c], v, g_b1s[c]), 0.f);
        }
        __syncthreads();
#pragma unroll 4
        for (int k = 0; k < 64; k++) {
            float a[8], bv[4];
            *(float4*)&a[0] = *(const float4*)&As[k][ro];
            *(float4*)&a[4] = *(const float4*)&As[k][ro + 64];
            *(float4*)&bv[0] = *(const float4*)&Xs[k][co];
#pragma unroll
            for (int i = 0; i < 8; i++)
#pragma unroll
                for (int j = 0; j < 4; j++) acc[i][j] = fmaf(a[i], bv[j], acc[i][j]);
        }
    }

    float* Y = g_y2 + (size_t)b * CO * NN + n0;
#pragma unroll
    for (int i = 0; i < 8; i++) {
        const int o = (i < 4) ? (ro + i) : (64 + ro + i - 4);
        const float bias = __ldg(&b2[o]);
        float4 v = make_float4(acc[i][0] + bias, acc[i][1] + bias,
                               acc[i][2] + bias, acc[i][3] + bias);
        *(float4*)&Y[(size_t)o * NN + co] = v;
    }
}

// =================================================================================
// BN2 + ReLU + transpose:  g_f2[b][n][c] = relu(a2[c]*y2[b][c][n] + b2s[c])
// =================================================================================
__global__ __launch_bounds__(256) void bn2t_kernel()
{
    __shared__ float tile[32][33];
    const int b = blockIdx.z, c0 = blockIdx.y * 32, n0 = blockIdx.x * 32;
    const int tx = threadIdx.x, ty = threadIdx.y;          // (32, 8)
#pragma unroll
    for (int i = 0; i < 4; i++) {
        const int c = c0 + ty + i * 8;
        const float v = g_y2[((size_t)b * CO + c) * NN + n0 + tx];
        tile[ty + i * 8][tx] = fmaxf(fmaf(g_a2[c], v, g_b2s[c]), 0.f);
    }
    __syncthreads();
#pragma unroll
    for (int i = 0; i < 4; i++) {
        const int n = n0 + ty + i * 8;
        g_f2[((size_t)b * NN + n) * CO + c0 + tx] = tile[tx][ty + i * 8];
    }
}

// =================================================================================
// kNN: one thread per centroid, streaming top-16 over a float4-packed smem tile
// {x, y, z, p2} -> single LDS.128 broadcast per candidate point.
// =================================================================================
__global__ __launch_bounds__(128) void knn_kernel(const float* __restrict__ points,
                                                  const float* __restrict__ cent)
{
    __shared__ float4 sp[2048];
    const int b = blockIdx.y;
    const int s = blockIdx.x * 128 + threadIdx.x;
    const float* P = points + (size_t)b * 3 * NN;
    const float* C = cent + (size_t)b * 3 * SS;

    const float cx = C[s], cy = C[SS + s], cz = C[2 * SS + s];
    const float c2 = __fadd_rn(__fadd_rn(__fmul_rn(cx, cx), __fmul_rn(cy, cy)),
                               __fmul_rn(cz, cz));

    float bd[KK]; int bi[KK];
#pragma unroll
    for (int j = 0; j < KK; j++) { bd[j] = 3.4e38f; bi[j] = 0x7fffffff; }
    float wd = 3.4e38f; int wi = 0x7fffffff; int ws = 0;

    for (int t0 = 0; t0 < NN; t0 += 2048) {
        __syncthreads();
        for (int i = threadIdx.x; i < 2048; i += 128) {
            const float x = P[t0 + i], y = P[NN + t0 + i], z = P[2 * NN + t0 + i];
            const float p2 = __fadd_rn(__fadd_rn(__fmul_rn(x, x), __fmul_rn(y, y)),
                                       __fmul_rn(z, z));
            sp[i] = make_float4(x, y, z, p2);
        }
        __syncthreads();
        for (int i = 0; i < 2048; i++) {
            const float4 v = sp[i];
            const float dot = __fadd_rn(__fadd_rn(__fmul_rn(cx, v.x), __fmul_rn(cy, v.y)),
                                        __fmul_rn(cz, v.z));
            const float d = __fsub_rn(__fadd_rn(c2, v.w), __fmul_rn(2.0f, dot));
            if (d < wd) {
                bd[ws] = d; bi[ws] = t0 + i;
                wd = bd[0]; wi = bi[0]; ws = 0;
#pragma unroll
                for (int j = 1; j < KK; j++) {
                    if (bd[j] > wd || (bd[j] == wd && bi[j] > wi)) {
                        wd = bd[j]; wi = bi[j]; ws = j;
                    }
                }
            }
        }
    }

    int* kn = g_knn + ((size_t)b * SS + s) * KK;
#pragma unroll
    for (int j = 0; j < KK; j++) kn[j] = bi[j];
}

// =================================================================================
// Gather + mean over K neighbors:  out[b][c][s] = mean_k f2[b][knn[b][s][k]][c]
// =================================================================================
__global__ __launch_bounds__(128) void gather_kernel(float* __restrict__ out)
{
    const int b = blockIdx.y;
    const int s = blockIdx.x;
    const int c = threadIdx.x;                             // 128 channels
    const int* kn = g_knn + ((size_t)b * SS + s) * KK;
    float acc = 0.f;
#pragma unroll
    for (int j = 0; j < KK; j++) {
        const int n = __ldg(&kn[j]);
        acc += g_f2[((size_t)b * NN + n) * CO + c];
    }
    out[((size_t)b * CO + c) * SS + s] = acc * (1.0f / KK);
}

// =================================================================================
extern "C" void kernel_launch(void* const* d_in, const int* in_sizes, int n_in,
                              void* d_out, int out_size)
{
    const float* feats  = (const float*)d_in[0];
    const float* points = (const float*)d_in[1];
    const float* W1     = (const float*)d_in[2];
    const float* b1     = (const float*)d_in[3];
    const float* gamma1 = (const float*)d_in[4];
    const float* beta1  = (const float*)d_in[5];
    const float* W2     = (const float*)d_in[6];
    const float* b2     = (const float*)d_in[7];
    const float* gamma2 = (const float*)d_in[8];
    const float* beta2  = (const float*)d_in[9];

    float* out  = (float*)d_out;
    float* cent = out + (size_t)BB * CO * SS;              // centroids tail: [B][3][S]

    fps_kernel<<<BB, 256>>>(points, cent);
    gemm1_kernel<<<dim3(NN / 64, BB), 256>>>(feats, W1, b1);
    stats_part_kernel<<<dim3(CO, BB), 256>>>(0);
    stats_fin_kernel<<<1, CO>>>(gamma1, beta1, 0);
    gemm2_kernel<<<dim3(NN / 64, BB), 256>>>(W2, b2);
    stats_part_kernel<<<dim3(CO, BB), 256>>>(1);
    stats_fin_kernel<<<1, CO>>>(gamma2, beta2, 1);
    bn2t_kernel<<<dim3(NN / 32, CO / 32, BB), dim3(32, 8)>>>();
    knn_kernel<<<dim3(SS / 128, BB), 128>>>(points, cent);
    gather_kernel<<<dim3(SS, BB), 128>>>(out);
}

// round 15
// speedup vs baseline: 1.1877x; 1.1877x over previous
#include <cuda_runtime.h>
#include <cuda_bf16.h>
#include <cstdint>

#define BB 8
#define NN 8192
#define CIN 64
#define CO 128
#define SS 2048
#define KK 16

typedef unsigned long long ull;

// ---------------- scratch (static device globals; no allocation) ----------------
__device__ float g_y1[(size_t)BB * CO * NN];     // conv1 pre-BN   [B][C][N]
__device__ float g_y2[(size_t)BB * CO * NN];     // conv2 pre-BN   [B][C][N]
__device__ float g_f2[(size_t)BB * NN * CO];     // conv2 post-BN  [B][N][C] (transposed)
__device__ float g_a1[CO], g_b1s[CO], g_a2[CO], g_b2s[CO];
__device__ float g_ps[2][CO][BB], g_pq[2][CO][BB];   // stats partials
__device__ int   g_knn[(size_t)BB * SS * KK];

// ---------------- packed f32x2 helpers (per-lane RN, identical to scalar) --------
__device__ __forceinline__ ull f2add(ull a, ull b) {
    ull r; asm("add.rn.f32x2 %0,%1,%2;" : "=l"(r) : "l"(a), "l"(b)); return r;
}
__device__ __forceinline__ ull f2mul(ull a, ull b) {
    ull r; asm("mul.rn.f32x2 %0,%1,%2;" : "=l"(r) : "l"(a), "l"(b)); return r;
}
__device__ __forceinline__ ull pack2(float lo, float hi) {
    ull r; asm("mov.b64 %0,{%1,%2};" : "=l"(r) : "f"(lo), "f"(hi)); return r;
}
__device__ __forceinline__ float2 unpack2(ull v) {
    float2 r; asm("mov.b64 {%0,%1},%2;" : "=f"(r.x), "=f"(r.y) : "l"(v)); return r;
}

// order-preserving float->u32 key (ascending bits == ascending float, any sign)
__device__ __forceinline__ unsigned fkey(float d) {
    const unsigned u = __float_as_uint(d);
    return ((int)u < 0) ? ~u : (u | 0x80000000u);
}

// =================================================================================
// FPS (R13, best known): one CTA per batch, 512 threads x 16 points packed f32x2,
// 2 barriers/iter, ping-pong atomicMax(float-bits) + lazy rescan + atomicMin.
// Distance formula matches reference bit-exactly: (dx*dx + dy*dy) + dz*dz, no FMA.
// =================================================================================
__global__ __launch_bounds__(512, 1) void fps_kernel(const float* __restrict__ points,
                                                     float* __restrict__ cent)
{
    __shared__ int sMaxI[2];   // float-bits of global max (dd >= 0 -> int order ok)
    __shared__ int sIdx[2];    // argmax index (first-index tiebreak)

    const int b = blockIdx.x;
    const int t = threadIdx.x;
    const int lane = t & 31;
    const float* P = points + (size_t)b * 3 * NN;
    float* C = cent + (size_t)b * 3 * SS;

    if (t == 0) { sMaxI[0] = 0; sMaxI[1] = 0; sIdx[0] = 0x7fffffff; sIdx[1] = 0x7fffffff; }

    const float x0 = __ldg(&P[0]);
    const float y0 = __ldg(&P[NN]);
    const float z0 = __ldg(&P[2 * NN]);
    const ull nx0 = pack2(-x0, -x0), ny0 = pack2(-y0, -y0), nz0 = pack2(-z0, -z0);

    const float2* Px = (const float2*)P;
    const float2* Py = (const float2*)(P + NN);
    const float2* Pz = (const float2*)(P + 2 * NN);

    ull px[8], py[8], pz[8];
    float dd[16];
#pragma unroll
    for (int q = 0; q < 8; q++) {
        const int i = t + 512 * q;
        const float2 vx = Px[i], vy = Py[i], vz = Pz[i];
        px[q] = pack2(vx.x, vx.y); py[q] = pack2(vy.x, vy.y); pz[q] = pack2(vz.x, vz.y);
        const ull dx = f2add(px[q], nx0);
        const ull dy = f2add(py[q], ny0);
        const ull dz = f2add(pz[q], nz0);
        const ull s = f2add(f2add(f2mul(dx, dx), f2mul(dy, dy)), f2mul(dz, dz));
        const float2 sv = unpack2(s);
        dd[2 * q] = sv.x; dd[2 * q + 1] = sv.y;
    }
    float wm;
    {
        float m = fmaxf(dd[0], dd[1]);
#pragma unroll
        for (int j = 2; j < 16; j += 2) m = fmaxf(m, fmaxf(dd[j], dd[j + 1]));
        wm = __uint_as_float(__reduce_max_sync(0xffffffffu, __float_as_uint(m)));
    }

    if (t == 0) { C[0] = x0; C[SS] = y0; C[2 * SS] = z0; }
    __syncthreads();   // slot init visible; first wm ready

    for (int s = 1; s < SS; s++) {
        const int c = s & 1;
        if (lane == 0) atomicMax(&sMaxI[c], __float_as_int(wm));
        __syncthreads();                                   // bar1
        const float gm = __int_as_float(sMaxI[c]);
        if (t == 0) { sMaxI[c ^ 1] = 0; sIdx[c ^ 1] = 0x7fffffff; }  // reset other slot
        if (wm == gm) {                                    // warp-uniform branch (~1 warp)
            int mi = 0x7fffffff;
#pragma unroll
            for (int q = 0; q < 8; q++) {
                const int base = 2 * (t + 512 * q);
                if (dd[2 * q] == gm)     mi = min(mi, base);
                if (dd[2 * q + 1] == gm) mi = min(mi, base + 1);
            }
            if (mi != 0x7fffffff) atomicMin(&sIdx[c], mi); // first-index tiebreak
        }
        __syncthreads();                                   // bar2
        const int widx = sIdx[c];
        const float cx = __ldg(&P[widx]);
        const float cy = __ldg(&P[NN + widx]);
        const float cz = __ldg(&P[2 * NN + widx]);
        if (t == 0) { C[s] = cx; C[SS + s] = cy; C[2 * SS + s] = cz; }

        const ull ncx = pack2(-cx, -cx), ncy = pack2(-cy, -cy), ncz = pack2(-cz, -cz);
#pragma unroll
        for (int q = 0; q < 8; q++) {
            const ull dx = f2add(px[q], ncx);
            const ull dy = f2add(py[q], ncy);
            const ull dz = f2add(pz[q], ncz);
            const ull d2 = f2add(f2add(f2mul(dx, dx), f2mul(dy, dy)), f2mul(dz, dz));
            const float2 dv = unpack2(d2);
            dd[2 * q]     = fminf(dd[2 * q], dv.x);
            dd[2 * q + 1] = fminf(dd[2 * q + 1], dv.y);
        }
        float m = fmaxf(dd[0], dd[1]);
#pragma unroll
        for (int j = 2; j < 16; j += 2) m = fmaxf(m, fmaxf(dd[j], dd[j + 1]));
        wm = __uint_as_float(__reduce_max_sync(0xffffffffu, __float_as_uint(m)));
    }
}

// =================================================================================
// GEMM1: y1[b][o][n] = W1[o][:] . feats[b][:][n] + b1[o]      (128x64 @ 64xN)
// =================================================================================
__global__ __launch_bounds__(256) void gemm1_kernel(const float* __restrict__ feats,
                                                    const float* __restrict__ W1,
                                                    const float* __restrict__ b1)
{
    __shared__ float As[CIN][CO];   // As[k][o]  (W transposed)
    __shared__ float Xs[CIN][64];
    const int b = blockIdx.y;
    const int n0 = blockIdx.x * 64;
    const int tid = threadIdx.x;
    const int tx = tid & 15, ty = tid >> 4;

    const float4* W4 = (const float4*)W1;                  // [128][16] float4
#pragma unroll
    for (int q = 0; q < 8; q++) {
        const int f = tid + 256 * q;                       // 0..2047
        const int o = f & 127;
        const int kq = f >> 7;                             // 0..15
        const float4 w = W4[o * 16 + kq];
        As[kq * 4 + 0][o] = w.x; As[kq * 4 + 1][o] = w.y;
        As[kq * 4 + 2][o] = w.z; As[kq * 4 + 3][o] = w.w;
    }
    const float* X = feats + (size_t)b * CIN * NN + n0;
#pragma unroll
    for (int r = 0; r < 16; r++) {
        const int e = tid + 256 * r;                       // 0..4095
        const int c = e >> 6, j = e & 63;
        Xs[c][j] = X[(size_t)c * NN + j];
    }
    __syncthreads();

    float acc[8][4];
#pragma unroll
    for (int i = 0; i < 8; i++)
#pragma unroll
        for (int j = 0; j < 4; j++) acc[i][j] = 0.f;

    const int ro = ty * 4, co = tx * 4;
#pragma unroll 4
    for (int k = 0; k < CIN; k++) {
        float a[8], bv[4];
        *(float4*)&a[0] = *(const float4*)&As[k][ro];
        *(float4*)&a[4] = *(const float4*)&As[k][ro + 64];
        *(float4*)&bv[0] = *(const float4*)&Xs[k][co];
#pragma unroll
        for (int i = 0; i < 8; i++)
#pragma unroll
            for (int j = 0; j < 4; j++) acc[i][j] = fmaf(a[i], bv[j], acc[i][j]);
    }

    float* Y = g_y1 + (size_t)b * CO * NN + n0;
#pragma unroll
    for (int i = 0; i < 8; i++) {
        const int o = (i < 4) ? (ro + i) : (64 + ro + i - 4);
        const float bias = __ldg(&b1[o]);
        float4 v = make_float4(acc[i][0] + bias, acc[i][1] + bias,
                               acc[i][2] + bias, acc[i][3] + bias);
        *(float4*)&Y[(size_t)o * NN + co] = v;
    }
}

// =================================================================================
// BN stats, two-stage. Stage A: grid (CO, BB) partial sums. Stage B: finalize.
// =================================================================================
__global__ __launch_bounds__(256) void stats_part_kernel(int which)
{
    const float* y = which ? g_y2 : g_y1;
    const int c = blockIdx.x, b = blockIdx.y, t = threadIdx.x;
    const int lane = t & 31, warp = t >> 5;
    const float* p = y + ((size_t)b * CO + c) * NN;
    float s = 0.f, q = 0.f;
    for (int i = t; i < NN; i += 256) { const float v = p[i]; s += v; q = fmaf(v, v, q); }
#pragma unroll
    for (int o = 16; o; o >>= 1) {
        s += __shfl_xor_sync(0xffffffffu, s, o);
        q += __shfl_xor_sync(0xffffffffu, q, o);
    }
    __shared__ float ss[8], qs[8];
    if (lane == 0) { ss[warp] = s; qs[warp] = q; }
    __syncthreads();
    if (t == 0) {
        float S = 0.f, Q = 0.f;
#pragma unroll
        for (int w = 0; w < 8; w++) { S += ss[w]; Q += qs[w]; }
        g_ps[which][c][b] = S; g_pq[which][c][b] = Q;
    }
}

__global__ __launch_bounds__(CO) void stats_fin_kernel(const float* __restrict__ gamma,
                                                       const float* __restrict__ beta,
                                                       int which)
{
    const int c = threadIdx.x;
    float S = 0.f, Q = 0.f;
#pragma unroll
    for (int b = 0; b < BB; b++) { S += g_ps[which][c][b]; Q += g_pq[which][c][b]; }
    const float mean = S * (1.f / 65536.f);
    const float var = Q * (1.f / 65536.f) - mean * mean;
    const float inv = rsqrtf(fmaxf(var, 0.f) + 1e-5f);
    const float av = gamma[c] * inv;
    if (which) { g_a2[c] = av; g_b2s[c] = beta[c] - mean * av; }
    else       { g_a1[c] = av; g_b1s[c] = beta[c] - mean * av; }
}

// =================================================================================
// GEMM2 with fused BN1+ReLU applied to the input tile   (128x128 @ 128xN)
// =================================================================================
__global__ __launch_bounds__(256) void gemm2_kernel(const float* __restrict__ W2,
                                                    const float* __restrict__ b2)
{
    __shared__ float As[64][CO];
    __shared__ float Xs[64][64];
    const int b = blockIdx.y, n0 = blockIdx.x * 64;
    const int tid = threadIdx.x, tx = tid & 15, ty = tid >> 4;

    float acc[8][4];
#pragma unroll
    for (int i = 0; i < 8; i++)
#pragma unroll
        for (int j = 0; j < 4; j++) acc[i][j] = 0.f;

    const float4* W4 = (const float4*)W2;                  // [128][32] float4
    const float* Ybase = g_y1 + (size_t)b * CO * NN + n0;
    const int ro = ty * 4, co = tx * 4;

    for (int kt = 0; kt < 2; kt++) {
        if (kt) __syncthreads();
#pragma unroll
        for (int q = 0; q < 8; q++) {
            const int f = tid + 256 * q;
            const int o = f & 127;
            const int kq = f >> 7;
            const float4 w = W4[o * 32 + kt * 16 + kq];
            As[kq * 4 + 0][o] = w.x; As[kq * 4 + 1][o] = w.y;
            As[kq * 4 + 2][o] = w.z; As[kq * 4 + 3][o] = w.w;
        }
#pragma unroll
        for (int r = 0; r < 16; r++) {
            const int e = tid + 256 * r;
            const int cl = e >> 6, j = e & 63;
            const int c = kt * 64 + cl;
            const float v = Ybase[(size_t)c * NN + j];
            Xs[cl][j] = fmaxf(fmaf(g_a1[c], v, g_b1s[c]), 0.f);
        }
        __syncthreads();
#pragma unroll 4
        for (int k = 0; k < 64; k++) {
            float a[8], bv[4];
            *(float4*)&a[0] = *(const float4*)&As[k][ro];
            *(float4*)&a[4] = *(const float4*)&As[k][ro + 64];
            *(float4*)&bv[0] = *(const float4*)&Xs[k][co];
#pragma unroll
            for (int i = 0; i < 8; i++)
#pragma unroll
                for (int j = 0; j < 4; j++) acc[i][j] = fmaf(a[i], bv[j], acc[i][j]);
        }
    }

    float* Y = g_y2 + (size_t)b * CO * NN + n0;
#pragma unroll
    for (int i = 0; i < 8; i++) {
        const int o = (i < 4) ? (ro + i) : (64 + ro + i - 4);
        const float bias = __ldg(&b2[o]);
        float4 v = make_float4(acc[i][0] + bias, acc[i][1] + bias,
                               acc[i][2] + bias, acc[i][3] + bias);
        *(float4*)&Y[(size_t)o * NN + co] = v;
    }
}

// =================================================================================
// BN2 + ReLU + transpose:  g_f2[b][n][c] = relu(a2[c]*y2[b][c][n] + b2s[c])
// =================================================================================
__global__ __launch_bounds__(256) void bn2t_kernel()
{
    __shared__ float tile[32][33];
    const int b = blockIdx.z, c0 = blockIdx.y * 32, n0 = blockIdx.x * 32;
    const int tx = threadIdx.x, ty = threadIdx.y;          // (32, 8)
#pragma unroll
    for (int i = 0; i < 4; i++) {
        const int c = c0 + ty + i * 8;
        const float v = g_y2[((size_t)b * CO + c) * NN + n0 + tx];
        tile[ty + i * 8][tx] = fmaxf(fmaf(g_a2[c], v, g_b2s[c]), 0.f);
    }
    __syncthreads();
#pragma unroll
    for (int i = 0; i < 4; i++) {
        const int n = n0 + ty + i * 8;
        g_f2[((size_t)b * NN + n) * CO + c0 + tx] = tile[tx][ty + i * 8];
    }
}

// =================================================================================
// kNN: 2 threads per centroid (each scans half the points, concurrently on two
// smem tile buffers), then an exact lexicographic (dist, idx) merge of the two
// top-16 lists via order-encoded u64 keys. The merged set equals the reference
// top-k set (16 smallest (d, idx)); output order is irrelevant (mean over K).
// Dynamic smem: 2 tiles x 2048 float4 = 64 KB; exchange overlays the upper tile.
// =================================================================================
__global__ __launch_bounds__(256) void knn_kernel(const float* __restrict__ points,
                                                  const float* __restrict__ cent)
{
    extern __shared__ float4 sp[];                 // [2][2048]
    const int b = blockIdx.y;
    const int t = threadIdx.x;
    const int half = t >> 7;                       // 0: points [0,4096), 1: [4096,8192)
    const int sl = t & 127;
    const int s = blockIdx.x * 128 + sl;
    const float* P = points + (size_t)b * 3 * NN;
    const float* C = cent + (size_t)b * 3 * SS;
    float4* myTile = sp + half * 2048;
    const int base = half * 4096;

    const float cx = C[s], cy = C[SS + s], cz = C[2 * SS + s];
    const float c2 = __fadd_rn(__fadd_rn(__fmul_rn(cx, cx), __fmul_rn(cy, cy)),
                               __fmul_rn(cz, cz));

    float bd[KK]; int bi[KK];
#pragma unroll
    for (int j = 0; j < KK; j++) { bd[j] = 3.4e38f; bi[j] = 0x7fffffff; }
    float wd = 3.4e38f; int wi = 0x7fffffff; int ws = 0;

    for (int tt = 0; tt < 4096; tt += 2048) {
        __syncthreads();
        // cooperative load of BOTH half-tiles (4096 float4) by all 256 threads
        for (int i = t; i < 4096; i += 256) {
            const int buf = i >> 11;               // 0 = lower tile, 1 = upper tile
            const int idx = i & 2047;
            const int gp = buf * 4096 + tt + idx;
            const float x = P[gp], y = P[NN + gp], z = P[2 * NN + gp];
            const float p2 = __fadd_rn(__fadd_rn(__fmul_rn(x, x), __fmul_rn(y, y)),
                                       __fmul_rn(z, z));
            sp[buf * 2048 + idx] = make_float4(x, y, z, p2);
        }
        __syncthreads();
        for (int i = 0; i < 2048; i++) {
            const float4 v = myTile[i];
            const float dot = __fadd_rn(__fadd_rn(__fmul_rn(cx, v.x), __fmul_rn(cy, v.y)),
                                        __fmul_rn(cz, v.z));
            const float d = __fsub_rn(__fadd_rn(c2, v.w), __fmul_rn(2.0f, dot));
            if (d < wd) {                          // exact within-half (idx increasing)
                bd[ws] = d; bi[ws] = base + tt + i;
                wd = bd[0]; wi = bi[0]; ws = 0;
#pragma unroll
                for (int j = 1; j < KK; j++) {
                    if (bd[j] > wd || (bd[j] == wd && bi[j] > wi)) {
                        wd = bd[j]; wi = bi[j]; ws = j;
                    }
                }
            }
        }
    }

    // ---- merge: upper half publishes keys, lower half folds them in ----
    __syncthreads();                               // all scans done; tiles dead
    ull* ex = (ull*)(sp + 2048);                   // overlays upper tile buffer
    if (half == 1) {
#pragma unroll
        for (int j = 0; j < KK; j++)
            ex[sl * KK + j] = ((ull)fkey(bd[j]) << 32) | (unsigned)bi[j];
    }
    __syncthreads();
    if (half == 0) {
        ull kk[KK];
        ull wk = 0; int wsI = 0;
#pragma unroll
        for (int j = 0; j < KK; j++) {
            kk[j] = ((ull)fkey(bd[j]) << 32) | (unsigned)bi[j];
            if (kk[j] > wk) { wk = kk[j]; wsI = j; }
        }
#pragma unroll
        for (int j = 0; j < KK; j++) {
            const ull cand = ex[sl * KK + j];
            if (cand < wk) {                       // lexicographic (d, idx)
                kk[wsI] = cand;
                wk = kk[0]; wsI = 0;
#pragma unroll
                for (int m = 1; m < KK; m++)
                    if (kk[m] > wk) { wk = kk[m]; wsI = m; }
            }
        }
        int* kn = g_knn + ((size_t)b * SS + s) * KK;
#pragma unroll
        for (int j = 0; j < KK; j++) kn[j] = (int)(unsigned)(kk[j] & 0xffffffffu);
    }
}

// =================================================================================
// Gather + mean over K neighbors:  out[b][c][s] = mean_k f2[b][knn[b][s][k]][c]
// =================================================================================
__global__ __launch_bounds__(128) void gather_kernel(float* __restrict__ out)
{
    const int b = blockIdx.y;
    const int s = blockIdx.x;
    const int c = threadIdx.x;                             // 128 channels
    const int* kn = g_knn + ((size_t)b * SS + s) * KK;
    float acc = 0.f;
#pragma unroll
    for (int j = 0; j < KK; j++) {
        const int n = __ldg(&kn[j]);
        acc += g_f2[((size_t)b * NN + n) * CO + c];
    }
    out[((size_t)b * CO + c) * SS + s] = acc * (1.0f / KK);
}

// =================================================================================
extern "C" void kernel_launch(void* const* d_in, const int* in_sizes, int n_in,
                              void* d_out, int out_size)
{
    const float* feats  = (const float*)d_in[0];
    const float* points = (const float*)d_in[1];
    const float* W1     = (const float*)d_in[2];
    const float* b1     = (const float*)d_in[3];
    const float* gamma1 = (const float*)d_in[4];
    const float* beta1  = (const float*)d_in[5];
    const float* W2     = (const float*)d_in[6];
    const float* b2     = (const float*)d_in[7];
    const float* gamma2 = (const float*)d_in[8];
    const float* beta2  = (const float*)d_in[9];

    float* out  = (float*)d_out;
    float* cent = out + (size_t)BB * CO * SS;              // centroids tail: [B][3][S]

    cudaFuncSetAttribute(knn_kernel, cudaFuncAttributeMaxDynamicSharedMemorySize, 65536);

    fps_kernel<<<BB, 512>>>(points, cent);
    gemm1_kernel<<<dim3(NN / 64, BB), 256>>>(feats, W1, b1);
    stats_part_kernel<<<dim3(CO, BB), 256>>>(0);
    stats_fin_kernel<<<1, CO>>>(gamma1, beta1, 0);
    gemm2_kernel<<<dim3(NN / 64, BB), 256>>>(W2, b2);
    stats_part_kernel<<<dim3(CO, BB), 256>>>(1);
    stats_fin_kernel<<<1, CO>>>(gamma2, beta2, 1);
    bn2t_kernel<<<dim3(NN / 32, CO / 32, BB), dim3(32, 8)>>>();
    knn_kernel<<<dim3(SS / 128, BB), 256, 65536>>>(points, cent);
    gather_kernel<<<dim3(SS, BB), 128>>>(out);
}